// round 3
// baseline (speedup 1.0000x reference)
#include <cuda_runtime.h>

#define K 8
#define LOG2PI 1.8378770664093453f
#define LOG2E  1.4426950408889634f

using u64 = unsigned long long;

__device__ __forceinline__ u64 pack2(float lo, float hi) {
    u64 r; asm("mov.b64 %0, {%1, %2};" : "=l"(r) : "f"(lo), "f"(hi)); return r;
}
__device__ __forceinline__ void unpack2(u64 v, float& lo, float& hi) {
    asm("mov.b64 {%0, %1}, %2;" : "=f"(lo), "=f"(hi) : "l"(v));
}
__device__ __forceinline__ u64 add2(u64 a, u64 b) {
    u64 r; asm("add.rn.f32x2 %0, %1, %2;" : "=l"(r) : "l"(a), "l"(b)); return r;
}
__device__ __forceinline__ u64 mul2(u64 a, u64 b) {
    u64 r; asm("mul.rn.f32x2 %0, %1, %2;" : "=l"(r) : "l"(a), "l"(b)); return r;
}
__device__ __forceinline__ u64 fma2(u64 a, u64 b, u64 c) {
    u64 r; asm("fma.rn.f32x2 %0, %1, %2, %3;" : "=l"(r) : "l"(a), "l"(b), "l"(c)); return r;
}
__device__ __forceinline__ float fast_ex2(float v) {
    float r; asm("ex2.approx.ftz.f32 %0, %1;" : "=f"(r) : "f"(v)); return r;
}
__device__ __forceinline__ float fast_rcp(float v) {
    float r; asm("rcp.approx.ftz.f32 %0, %1;" : "=f"(r) : "f"(v)); return r;
}
// ex2 on both halves of a packed pair
__device__ __forceinline__ u64 ex2_pair(u64 t) {
    float lo, hi; unpack2(t, lo, hi);
    return pack2(fast_ex2(lo), fast_ex2(hi));
}

__global__ void __launch_bounds__(128)
gmm_hscore_kernel(const float4* __restrict__ x4, float4* __restrict__ out4,
                  const float* __restrict__ mean, const float* __restrict__ logvar,
                  const float* __restrict__ logweight, int n4)
{
    // --- in-block setup: 8 threads compute per-component constants ---
    __shared__ float2 s_negmu[K], s_a2[K], s_iv[K];
    int tid = threadIdx.x;
    if (tid < K) {
        float mu = mean[tid];
        float lv = logvar[tid];
        float lw = logweight[tid];
        float iv = expf(-lv);                        // 1/var, precise
        float a2 = (lw - 0.5f * (lv + LOG2PI)) * LOG2E;  // log2 amplitude
        s_negmu[tid] = make_float2(-mu, -mu);
        s_a2[tid]    = make_float2(a2, a2);
        s_iv[tid]    = make_float2(iv, iv);
    }
    __syncthreads();

    // broadcast constants into packed registers (LDS.64, conflict-free broadcast)
    u64 negmu[K], a2c[K], ivc[K];
#pragma unroll
    for (int k = 0; k < K; k++) {
        negmu[k] = *reinterpret_cast<const u64*>(&s_negmu[k]);
        a2c[k]   = *reinterpret_cast<const u64*>(&s_a2[k]);
        ivc[k]   = *reinterpret_cast<const u64*>(&s_iv[k]);
    }
    const u64 negC2   = pack2(-0.5f * LOG2E, -0.5f * LOG2E);
    const u64 negone2 = pack2(-1.0f, -1.0f);
    const u64 neghalf2 = pack2(-0.5f, -0.5f);

    int i = blockIdx.x * 128 + tid;
    if (i >= n4) return;

    float4 xv = x4[i];
    u64 x0 = pack2(xv.x, xv.y);
    u64 x1 = pack2(xv.z, xv.w);

    u64 mpdf0 = 0, mds0 = 0, dd0 = 0;   // bitwise {0.f, 0.f}
    u64 mpdf1 = 0, mds1 = 0, dd1 = 0;

#pragma unroll
    for (int k = 0; k < K; k++) {
        u64 d0 = add2(x0, negmu[k]);            // diff = x - mu
        u64 d1 = add2(x1, negmu[k]);
        u64 s0 = mul2(d0, d0);                  // diff^2
        u64 s1 = mul2(d1, d1);
        u64 e0 = mul2(s0, ivc[k]);              // diff^2 / var
        u64 e1 = mul2(s1, ivc[k]);
        u64 t0 = fma2(negC2, e0, a2c[k]);       // log2 p
        u64 t1 = fma2(negC2, e1, a2c[k]);
        u64 p0 = ex2_pair(t0);                  // p = weight * N(x;mu,var)
        u64 p1 = ex2_pair(t1);
        u64 q0 = mul2(p0, ivc[k]);              // p/var
        u64 q1 = mul2(p1, ivc[k]);
        mpdf0 = add2(mpdf0, p0);
        mpdf1 = add2(mpdf1, p1);
        mds0  = fma2(q0, d0, mds0);             // = -mdpdf
        mds1  = fma2(q1, d1, mds1);
        u64 m0 = add2(e0, negone2);             // diff^2/var - 1
        u64 m1 = add2(e1, negone2);
        dd0 = fma2(q0, m0, dd0);                // ddpdf
        dd1 = fma2(q1, m1, dd1);
    }

    // epilogue
    float lo, hi;
    unpack2(mpdf0, lo, hi);
    u64 rm0 = pack2(fast_rcp(lo), fast_rcp(hi));
    unpack2(mpdf1, lo, hi);
    u64 rm1 = pack2(fast_rcp(lo), fast_rcp(hi));

    u64 dl0 = mul2(mds0, rm0);                  // = -dlnpdf (squared below)
    u64 dl1 = mul2(mds1, rm1);
    u64 g0  = mul2(dd0, rm0);                   // ddpdf/mpdf
    u64 g1  = mul2(dd1, rm1);
    u64 u0  = mul2(dl0, dl0);
    u64 u1  = mul2(dl1, dl1);
    u64 h0  = fma2(neghalf2, u0, g0);           // -0.5*dl^2 + dd/m
    u64 h1  = fma2(neghalf2, u1, g1);

    float4 ov;
    unpack2(h0, ov.x, ov.y);
    unpack2(h1, ov.z, ov.w);
    out4[i] = ov;
}

extern "C" void kernel_launch(void* const* d_in, const int* in_sizes, int n_in,
                              void* d_out, int out_size) {
    const float* x         = (const float*)d_in[0];
    const float* mean      = (const float*)d_in[1];
    const float* logvar    = (const float*)d_in[2];
    const float* logweight = (const float*)d_in[3];
    float* out = (float*)d_out;

    int n  = in_sizes[0];
    int n4 = n >> 2;                 // 1,048,576 float4 elements

    int threads = 128;
    int blocks  = (n4 + threads - 1) / threads;
    gmm_hscore_kernel<<<blocks, threads>>>(
        (const float4*)x, (float4*)out, mean, logvar, logweight, n4);
}